// round 11
// baseline (speedup 1.0000x reference)
#include <cuda_runtime.h>

#define H_IMG 512
#define W_IMG 512
#define NPLANES 96            // 32 * 3
#define TW 32
#define SEG 128               // output rows per block
#define IW 42                 // TW + 10
#define SROWS 42              // staged input rows (iteration 0)
#define SS 43                 // staged-input smem row stride (conflict-free)
#define RING 48               // hconv ring rows
#define MS 33                 // intermediate smem row stride (conflict-free)
#define NT 256
#define NBX 16                // 512/32
#define NBY 4                 // 512/128
#define NBLK (NBX * NBY * NPLANES)   // 6144
#define C1F 6.5025f
#define C2F 58.5225f
#define NPIX 25165824.0       // 32*3*512*512

__device__ float g_partials[NBLK];
__device__ unsigned int g_count = 0;

#define W11_INIT {0.00102838f, 0.00759871f, 0.03600077f, 0.10936070f, \
                  0.21300560f, 0.26601180f, 0.21300560f, 0.10936070f, \
                  0.03600077f, 0.00759871f, 0.00102838f}

__global__ void __launch_bounds__(NT, 5) ssim_main(const float* __restrict__ gen,
                                                   const float* __restrict__ ref,
                                                   float* __restrict__ out) {
    __shared__ float sg[SROWS * SS];   // staged gen (scaled)
    __shared__ float sr[SROWS * SS];   // staged ref (scaled)
    __shared__ float m1[RING * MS];    // ring: conv_h(g)
    __shared__ float m2[RING * MS];    // ring: conv_h(r)
    __shared__ float mss[RING * MS];   // ring: conv_h(g^2 + r^2)
    __shared__ float mgr[RING * MS];   // ring: conv_h(g*r)
    __shared__ float wsum[8];
    __shared__ double dsum[8];
    __shared__ bool is_last;

    const float W11[11] = W11_INIT;    // compile-time consts -> FFMA-imm

    const int tid = threadIdx.x;
    const int lane = tid & 31;
    const int wrp = tid >> 5;
    const int x0 = blockIdx.x * TW;
    const int y0 = blockIdx.y * SEG;
    const size_t pb = (size_t)blockIdx.z * (size_t)(H_IMG * W_IMG);
    const float* gp = gen + pb;
    const float* rp = ref + pb;

    // stage NROWS input rows starting at image row GY0 into sgr slots 0..NROWS-1
#define STAGE_ROWS(GY0, NROWS)                                            \
    for (int r_ = wrp; r_ < (NROWS); r_ += 8) {                           \
        int gy_ = (GY0) + r_;                                             \
        bool rowok_ = (unsigned)gy_ < (unsigned)H_IMG;                    \
        const float* grow_ = gp + (long)gy_ * W_IMG;                      \
        const float* rrow_ = rp + (long)gy_ * W_IMG;                      \
        float* sgrow_ = sg + r_ * SS;                                     \
        float* srrow_ = sr + r_ * SS;                                     \
        _Pragma("unroll")                                                 \
        for (int h2_ = 0; h2_ < 2; h2_++) {                               \
            int c_ = lane + h2_ * 32;                                     \
            if (c_ < IW) {                                                \
                int gx_ = x0 + c_ - 5;                                    \
                bool ok_ = rowok_ & ((unsigned)gx_ < (unsigned)W_IMG);    \
                sgrow_[c_] = ok_ ? fmaf(grow_[gx_], 0.5f, 0.5f) : 0.f;    \
                srrow_[c_] = ok_ ? fmaf(rrow_[gx_], 0.5f, 0.5f) : 0.f;    \
            }                                                             \
        }                                                                 \
    }

#define HCONV_STORE(SRC, DST)                                             \
        {                                                                 \
            float s[4] = {0.f, 0.f, 0.f, 0.f};                            \
            _Pragma("unroll")                                             \
            for (int k = 0; k < 11; k++) {                                \
                _Pragma("unroll")                                         \
                for (int j = 0; j < 4; j++)                               \
                    s[j] = fmaf(W11[k], SRC[k + j], s[j]);                \
            }                                                             \
            _Pragma("unroll")                                             \
            for (int j = 0; j < 4; j++) DST[o + j] = s[j];                \
        }

    // hconv one 4-col chunk: sgr slot SRCROW -> ring slot SLOT
#define HCONV_ALL(SRCROW, SLOT, C0)                                       \
    {                                                                     \
        const float* sgr_ = sg + (SRCROW) * SS + (C0);                    \
        const float* srr_ = sr + (SRCROW) * SS + (C0);                    \
        const int o = (SLOT) * MS + (C0);                                 \
        float a[14], b[14];                                               \
        _Pragma("unroll")                                                 \
        for (int t = 0; t < 14; t++) { a[t] = sgr_[t]; b[t] = srr_[t]; }  \
        HCONV_STORE(a, m1)                                                \
        HCONV_STORE(b, m2)                                                \
        _Pragma("unroll")                                                 \
        for (int t = 0; t < 14; t++) {                                    \
            float pa = a[t];                                              \
            float pbv = b[t];                                             \
            a[t] = fmaf(pa, pa, pbv * pbv);                               \
            b[t] = pa * pbv;                                              \
        }                                                                 \
        HCONV_STORE(a, mss)                                               \
        HCONV_STORE(b, mgr)                                               \
    }

    // vertical conv with ring wrap; bb = ring base row for this thread
#define VCONVW(MARR, OUT)                                                 \
        {                                                                 \
            float v[14];                                                  \
            _Pragma("unroll")                                             \
            for (int t = 0; t < 14; t++) {                                \
                int s_ = bb + t;                                          \
                if (s_ >= RING) s_ -= RING;                               \
                v[t] = MARR[s_ * MS + c];                                 \
            }                                                             \
            _Pragma("unroll")                                             \
            for (int j = 0; j < 4; j++) {                                 \
                float acc = 0.f;                                          \
                _Pragma("unroll")                                         \
                for (int k = 0; k < 11; k++)                              \
                    acc = fmaf(W11[k], v[j + k], acc);                    \
                OUT[j] = acc;                                             \
            }                                                             \
        }

    // ---- preload iteration-0 staged rows (42) ----
    STAGE_ROWS(y0 - 5, SROWS)
    __syncthreads();

    float lsum = 0.f;

#pragma unroll
    for (int it = 0; it < 4; it++) {
        // ---- Phase A: horizontal conv of this iteration's new hrows ----
        if (it == 0) {
            // 42 rows x 8 chunks = 336 items; ring slot == hrow (0..41)
            for (int item = tid; item < SROWS * 8; item += NT) {
                int r = item >> 3;
                int c0 = (item & 7) << 2;
                HCONV_ALL(r, r, c0)
            }
        } else {
            // 32 rows x 8 chunks = 256 items, single balanced pass
            int r = tid >> 3;
            int c0 = (tid & 7) << 2;
            int slot = (it == 1) ? ((r < 6) ? 42 + r : r - 6)
                     : (it == 2) ? ((r < 22) ? 26 + r : r - 22)
                                 : 10 + r;                 // it == 3
            HCONV_ALL(r, slot, c0)
        }
        __syncthreads();

        // ---- Phase B: vertical conv + SSIM for 32 output rows; then stage
        //      next iteration's 32 input rows (disjoint smem) ----
        {
            const int c = lane;
            const int r0 = wrp << 2;
            const int base = (it == 1) ? 32 : (it == 2) ? 16 : 0;
            const int bb = base + r0;

            float q[4], p[4];          // mu1^2+mu2^2, mu1*mu2
            {
                float o1[4], o2[4];
                VCONVW(m1, o1)
                VCONVW(m2, o2)
#pragma unroll
                for (int j = 0; j < 4; j++) {
                    q[j] = fmaf(o1[j], o1[j], o2[j] * o2[j]);
                    p[j] = o1[j] * o2[j];
                }
            }
            float dden[4];
            {
                float oss[4];
                VCONVW(mss, oss)
#pragma unroll
                for (int j = 0; j < 4; j++)
                    dden[j] = (q[j] + C1F) * (oss[j] - q[j] + C2F);
            }
            {
                float ogr[4];
                VCONVW(mgr, ogr)
#pragma unroll
                for (int j = 0; j < 4; j++) {
                    float num = fmaf(2.f, p[j], C1F) * fmaf(2.f, ogr[j] - p[j], C2F);
                    lsum += __fdividef(num, dden[j]);
                }
            }
        }

        if (it < 3) {
            // stage input rows for hconv of h = 32*(it+1)+10 .. +41
            STAGE_ROWS(y0 + 32 * (it + 1) + 5, 32)
        }
        __syncthreads();
    }

#undef STAGE_ROWS
#undef HCONV_STORE
#undef HCONV_ALL
#undef VCONVW

    // ---- Block reduction (fp32) ----
#pragma unroll
    for (int off = 16; off > 0; off >>= 1)
        lsum += __shfl_xor_sync(0xffffffffu, lsum, off);
    if (lane == 0) wsum[wrp] = lsum;
    __syncthreads();

    if (tid == 0) {
        float s = 0.f;
#pragma unroll
        for (int i = 0; i < 8; i++) s += wsum[i];
        int bid = blockIdx.x + NBX * (blockIdx.y + NBY * blockIdx.z);
        g_partials[bid] = s;
        __threadfence();
        unsigned int t = atomicAdd(&g_count, 1u);
        is_last = (t == (unsigned)(NBLK - 1));
    }
    __syncthreads();

    // ---- Last block: deterministic final reduction ----
    if (is_last) {
        __threadfence();
        double acc = 0.0;
        for (int i = tid; i < NBLK; i += NT)
            acc += (double)g_partials[i];
#pragma unroll
        for (int off = 16; off > 0; off >>= 1)
            acc += __shfl_xor_sync(0xffffffffu, acc, off);
        if (lane == 0) dsum[wrp] = acc;
        __syncthreads();
        if (tid == 0) {
            double s = 0.0;
#pragma unroll
            for (int i = 0; i < 8; i++) s += dsum[i];
            out[0] = (float)(1.0 - s / NPIX);
            g_count = 0;   // self-reset -> graph-replay deterministic
        }
    }
}

extern "C" void kernel_launch(void* const* d_in, const int* in_sizes, int n_in,
                              void* d_out, int out_size) {
    const float* gen = (const float*)d_in[0];
    const float* ref = (const float*)d_in[1];
    float* out = (float*)d_out;

    dim3 grid(NBX, NBY, NPLANES);
    ssim_main<<<grid, NT>>>(gen, ref, out);
}

// round 12
// speedup vs baseline: 1.7133x; 1.7133x over previous
#include <cuda_runtime.h>

#define H_IMG 512
#define W_IMG 512
#define NPLANES 96            // 32 * 3
#define TW 32
#define TH 32
#define IW 42                 // TW + 10
#define IH 42                 // TH + 10
#define SS2 43                // staged (g,r) float2 stride
#define MS2 33                // intermediate float2 stride
#define NT 256
#define NBX 16                // 512/32
#define NBY 16                // 512/32
#define NBLK (NBX * NBY * NPLANES)   // 24576
#define C1F 6.5025f
#define C2F 58.5225f
#define NPIX 25165824.0       // 32*3*512*512

__device__ float g_partials[NBLK];
__device__ unsigned int g_count = 0;

#define W11_INIT {0.00102838f, 0.00759871f, 0.03600077f, 0.10936070f, \
                  0.21300560f, 0.26601180f, 0.21300560f, 0.10936070f, \
                  0.03600077f, 0.00759871f, 0.00102838f}

__global__ void __launch_bounds__(NT, 5) ssim_main(const float* __restrict__ gen,
                                                   const float* __restrict__ ref,
                                                   float* __restrict__ out) {
    __shared__ float2 sgr[IH * SS2];   // (g, r) scaled
    __shared__ float2 pm[IH * MS2];    // (conv_h g, conv_h r)
    __shared__ float2 pv[IH * MS2];    // (conv_h g^2+r^2, conv_h g*r)
    __shared__ float wsum[8];
    __shared__ double dsum[8];
    __shared__ bool is_last;

    const float W11[11] = W11_INIT;    // compile-time consts -> FFMA-imm

    const int tid = threadIdx.x;
    const int lane = tid & 31;
    const int wrp = tid >> 5;
    const int x0 = blockIdx.x * TW;
    const int y0 = blockIdx.y * TH;
    const size_t pb = (size_t)blockIdx.z * (size_t)(H_IMG * W_IMG);
    const float* gp = gen + pb;
    const float* rp = ref + pb;

    // ---- Stage 0: warp-per-row coalesced load, scale, pack (g,r), zero-pad ----
    const bool interior = (x0 >= 5) & (x0 + IW - 5 <= W_IMG) &
                          (y0 >= 5) & (y0 + IH - 5 <= H_IMG);
    if (interior) {
        const float* gb = gp + (long)(y0 - 5) * W_IMG + (x0 - 5);
        const float* rb = rp + (long)(y0 - 5) * W_IMG + (x0 - 5);
#pragma unroll
        for (int r = wrp; r < IH; r += 8) {
            const float* grow = gb + (long)r * W_IMG;
            const float* rrow = rb + (long)r * W_IMG;
            float2* srow = sgr + r * SS2;
            srow[lane] = make_float2(fmaf(grow[lane], 0.5f, 0.5f),
                                     fmaf(rrow[lane], 0.5f, 0.5f));
            if (lane < IW - 32)
                srow[lane + 32] = make_float2(fmaf(grow[lane + 32], 0.5f, 0.5f),
                                              fmaf(rrow[lane + 32], 0.5f, 0.5f));
        }
    } else {
#pragma unroll
        for (int r = wrp; r < IH; r += 8) {
            int gy = y0 + r - 5;
            bool rowok = (unsigned)gy < (unsigned)H_IMG;
            const float* grow = gp + (long)gy * W_IMG;
            const float* rrow = rp + (long)gy * W_IMG;
            float2* srow = sgr + r * SS2;
#pragma unroll
            for (int h = 0; h < 2; h++) {
                int c = lane + h * 32;
                if (c < IW) {
                    int gx = x0 + c - 5;
                    bool ok = rowok && ((unsigned)gx < (unsigned)W_IMG);
                    srow[c] = ok ? make_float2(fmaf(grow[gx], 0.5f, 0.5f),
                                               fmaf(rrow[gx], 0.5f, 0.5f))
                                 : make_float2(0.f, 0.f);
                }
            }
        }
    }
    __syncthreads();

    // ---- Stage 1: horizontal conv, ROW-FASTEST item map (item = ch*42 + r)
    //      -> warp lanes are consecutive rows, same chunk: conflict-free 64-bit ----
    for (int item = tid; item < IH * 8; item += NT) {
        int ch = item / IH;            // const-division: mul-hi + shift
        int r = item - ch * IH;
        int c0 = ch << 2;
        const float2* srow = sgr + r * SS2 + c0;
        const int o = r * MS2 + c0;

        float2 w[14];
#pragma unroll
        for (int t = 0; t < 14; t++) w[t] = srow[t];

        // first moments (g, r) -> float2 store
        {
            float s1[4] = {0.f, 0.f, 0.f, 0.f};
            float s2[4] = {0.f, 0.f, 0.f, 0.f};
#pragma unroll
            for (int k = 0; k < 11; k++) {
#pragma unroll
                for (int j = 0; j < 4; j++) {
                    s1[j] = fmaf(W11[k], w[k + j].x, s1[j]);
                    s2[j] = fmaf(W11[k], w[k + j].y, s2[j]);
                }
            }
#pragma unroll
            for (int j = 0; j < 4; j++) pm[o + j] = make_float2(s1[j], s2[j]);
        }

        // in-place transform: w <- (g^2 + r^2, g*r)
#pragma unroll
        for (int t = 0; t < 14; t++) {
            float gv = w[t].x;
            float rv = w[t].y;
            w[t] = make_float2(fmaf(gv, gv, rv * rv), gv * rv);
        }

        // second moments (ss, gr) -> float2 store
        {
            float s3[4] = {0.f, 0.f, 0.f, 0.f};
            float s4[4] = {0.f, 0.f, 0.f, 0.f};
#pragma unroll
            for (int k = 0; k < 11; k++) {
#pragma unroll
                for (int j = 0; j < 4; j++) {
                    s3[j] = fmaf(W11[k], w[k + j].x, s3[j]);
                    s4[j] = fmaf(W11[k], w[k + j].y, s4[j]);
                }
            }
#pragma unroll
            for (int j = 0; j < 4; j++) pv[o + j] = make_float2(s3[j], s4[j]);
        }
    }
    __syncthreads();

    // ---- Stage 2: vertical conv (4 rows/thread), streaming SSIM combine ----
    float lsum = 0.f;
    {
        const int c = lane;
        const int r0 = wrp << 2;       // 8 warps * 4 rows = 32

        float q[4], p[4];              // mu1^2+mu2^2, mu1*mu2
        {
            float2 v[14];
#pragma unroll
            for (int t = 0; t < 14; t++) v[t] = pm[(r0 + t) * MS2 + c];
#pragma unroll
            for (int j = 0; j < 4; j++) {
                float o1 = 0.f, o2 = 0.f;
#pragma unroll
                for (int k = 0; k < 11; k++) {
                    o1 = fmaf(W11[k], v[j + k].x, o1);
                    o2 = fmaf(W11[k], v[j + k].y, o2);
                }
                q[j] = fmaf(o1, o1, o2 * o2);
                p[j] = o1 * o2;
            }
        }
        {
            float2 v[14];
#pragma unroll
            for (int t = 0; t < 14; t++) v[t] = pv[(r0 + t) * MS2 + c];
#pragma unroll
            for (int j = 0; j < 4; j++) {
                float oss = 0.f, ogr = 0.f;
#pragma unroll
                for (int k = 0; k < 11; k++) {
                    oss = fmaf(W11[k], v[j + k].x, oss);
                    ogr = fmaf(W11[k], v[j + k].y, ogr);
                }
                float num = fmaf(2.f, p[j], C1F) * fmaf(2.f, ogr - p[j], C2F);
                float den = (q[j] + C1F) * (oss - q[j] + C2F);
                lsum += __fdividef(num, den);
            }
        }
    }

    // ---- Block reduction (fp32) ----
#pragma unroll
    for (int off = 16; off > 0; off >>= 1)
        lsum += __shfl_xor_sync(0xffffffffu, lsum, off);
    if (lane == 0) wsum[wrp] = lsum;
    __syncthreads();

    if (tid == 0) {
        float s = 0.f;
#pragma unroll
        for (int i = 0; i < 8; i++) s += wsum[i];
        int bid = blockIdx.x + NBX * (blockIdx.y + NBY * blockIdx.z);
        g_partials[bid] = s;
        __threadfence();
        unsigned int t = atomicAdd(&g_count, 1u);
        is_last = (t == (unsigned)(NBLK - 1));
    }
    __syncthreads();

    // ---- Last block: deterministic final reduction ----
    if (is_last) {
        __threadfence();
        double acc = 0.0;
        for (int i = tid; i < NBLK; i += NT)
            acc += (double)g_partials[i];
#pragma unroll
        for (int off = 16; off > 0; off >>= 1)
            acc += __shfl_xor_sync(0xffffffffu, acc, off);
        if (lane == 0) dsum[wrp] = acc;
        __syncthreads();
        if (tid == 0) {
            double s = 0.0;
#pragma unroll
            for (int i = 0; i < 8; i++) s += dsum[i];
            out[0] = (float)(1.0 - s / NPIX);
            g_count = 0;   // self-reset -> graph-replay deterministic
        }
    }
}

extern "C" void kernel_launch(void* const* d_in, const int* in_sizes, int n_in,
                              void* d_out, int out_size) {
    const float* gen = (const float*)d_in[0];
    const float* ref = (const float*)d_in[1];
    float* out = (float*)d_out;

    dim3 grid(NBX, NBY, NPLANES);
    ssim_main<<<grid, NT>>>(gen, ref, out);
}